// round 14
// baseline (speedup 1.0000x reference)
#include <cuda_runtime.h>
#include <cstdint>

#define BZ     64
#define NC     2048
#define H      14
#define HW     196
#define NCLS   1000
#define SPLITS 8
#define CPB    256
#define TILE_C 16
#define NSTAGE 16            // CPB / TILE_C
#define NBUF   5
#define TPB    256
#define PADW   208           // channel stride (words): conflict-free LDS.64
#define NPAIR  105
#define NACC   15            // max packed accumulators per 8-way group
#define MARGINV 70.0f
#define THRV    125.0f
#define PD_EPS  1e-6f

typedef unsigned long long ull;

// scratch (device globals; no allocations allowed)
__device__ float g_G[BZ * SPLITS * NPAIR];
__device__ float g_cam[BZ * SPLITS * 3 * HW];
__device__ float g_rs[BZ * SPLITS * H];
__device__ float g_cem[BZ * SPLITS];
__device__ float g_ces[BZ * SPLITS];
__device__ float g_r[BZ];
__device__ int   g_cnt_b[BZ];
__device__ int   g_cnt_all;

// ---------------- f32x2 helpers ----------------
__device__ __forceinline__ ull pk2(float lo, float hi) {
    ull r; asm("mov.b64 %0,{%1,%2};" : "=l"(r) : "f"(lo), "f"(hi)); return r;
}
__device__ __forceinline__ void upk2(float& lo, float& hi, ull v) {
    asm("mov.b64 {%0,%1},%2;" : "=f"(lo), "=f"(hi) : "l"(v));
}
__device__ __forceinline__ ull fma2(ull a, ull b, ull c) {
    ull d; asm("fma.rn.f32x2 %0,%1,%2,%3;" : "=l"(d) : "l"(a), "l"(b), "l"(c)); return d;
}
__device__ __forceinline__ ull add2(ull a, ull b) {
    ull d; asm("add.rn.f32x2 %0,%1,%2;" : "=l"(d) : "l"(a), "l"(b)); return d;
}

// ---------------------------------------------------------------------------
// cp.async prefetch of one 16-channel tile into stride-PADW smem
// ---------------------------------------------------------------------------
__device__ __forceinline__ void prefetch_tile(const float* __restrict__ src_base,
                                              float* dst, int t) {
#pragma unroll
    for (int it = 0; it < 4; it++) {
        int q = t + it * TPB;            // 784 float4 transfers (16*49)
        if (q < TILE_C * 49) {
            int cc = q / 49;
            int p4 = q - cc * 49;
            const float* src = src_base + cc * HW + p4 * 4;
            unsigned dsts = (unsigned)__cvta_generic_to_shared(dst + cc * PADW + p4 * 4);
            asm volatile("cp.async.cg.shared.global [%0], [%1], 16;\n"
                         :: "r"(dsts), "l"(src));
        }
    }
}

// ---------------------------------------------------------------------------
// Gram 8-way group for one channel at column-pair u (row-contiguous LDS.64).
//   Q = (k-parity, l-parity) quarter; S = 0: a in {0,1}, S = 1: a in {2..6}
// ---------------------------------------------------------------------------
template<int Q, int S>
__device__ __forceinline__ void gram_g(const float* __restrict__ p,
                                       ull* __restrict__ acc) {
    if (Q == 0 || Q == 3) {
        const int off = (Q == 0) ? 0 : 14;
        if (S == 0) {
            ull r[7];
#pragma unroll
            for (int a = 0; a < 7; a++) r[a] = *(const ull*)(p + 28 * a + off);
#pragma unroll
            for (int b = 0; b < 7; b++) acc[b] = fma2(r[0], r[b], acc[b]);
#pragma unroll
            for (int b = 1; b < 7; b++) acc[6 + b] = fma2(r[1], r[b], acc[6 + b]);
        } else {
            ull r[5];
#pragma unroll
            for (int a = 0; a < 5; a++) r[a] = *(const ull*)(p + 28 * (a + 2) + off);
            int ii = 0;
#pragma unroll
            for (int a = 0; a < 5; a++)
#pragma unroll
                for (int b = a; b < 5; b++) { acc[ii] = fma2(r[a], r[b], acc[ii]); ii++; }
        }
    } else if (Q == 1) {             // k even, l odd, b >= a
        if (S == 0) {
            ull e0 = *(const ull*)(p);
            ull e1 = *(const ull*)(p + 28);
            ull o[7];
#pragma unroll
            for (int b = 0; b < 7; b++) o[b] = *(const ull*)(p + 28 * b + 14);
#pragma unroll
            for (int b = 0; b < 7; b++) acc[b] = fma2(e0, o[b], acc[b]);
#pragma unroll
            for (int b = 1; b < 7; b++) acc[6 + b] = fma2(e1, o[b], acc[6 + b]);
        } else {
            ull e[5], o[5];
#pragma unroll
            for (int a = 0; a < 5; a++) {
                e[a] = *(const ull*)(p + 28 * (a + 2));
                o[a] = *(const ull*)(p + 28 * (a + 2) + 14);
            }
            int ii = 0;
#pragma unroll
            for (int a = 0; a < 5; a++)
#pragma unroll
                for (int b = a; b < 5; b++) { acc[ii] = fma2(e[a], o[b], acc[ii]); ii++; }
        }
    } else {                          // Q2: k odd, l even, b >= a+1
        if (S == 0) {
            ull o0 = *(const ull*)(p + 14);
            ull o1 = *(const ull*)(p + 28 + 14);
            ull e[6];
#pragma unroll
            for (int b = 0; b < 6; b++) e[b] = *(const ull*)(p + 28 * (b + 1));
#pragma unroll
            for (int b = 0; b < 6; b++) acc[b] = fma2(o0, e[b], acc[b]);
#pragma unroll
            for (int b = 1; b < 6; b++) acc[5 + b] = fma2(o1, e[b], acc[5 + b]);
        } else {
            ull o[4], e[4];
#pragma unroll
            for (int a = 0; a < 4; a++) {
                o[a] = *(const ull*)(p + 28 * (a + 2) + 14);
                e[a] = *(const ull*)(p + 28 * (a + 3));
            }
            int ii = 0;
#pragma unroll
            for (int a = 0; a < 4; a++)
#pragma unroll
                for (int b = a; b < 4; b++) { acc[ii] = fma2(o[a], e[b], acc[ii]); ii++; }
        }
    }
}

// ---------------------------------------------------------------------------
// Fused kernel: 8-way low-reg Gram + grid 512 for true 3-CTA/SM occupancy
// ---------------------------------------------------------------------------
__global__ void __launch_bounds__(TPB, 3)
k1_fused(const float* __restrict__ feat,
         const float* __restrict__ W,
         const int*   __restrict__ idx,
         const float* __restrict__ pred,
         const int*   __restrict__ cla,
         const float* __restrict__ seg,
         float*       __restrict__ out) {
    extern __shared__ float sh[];
    float* tiles = sh;                                      // 5*16*208 = 16640 floats
    ull*   w0p   = (ull*)(sh + NBUF * TILE_C * PADW);       // CPB/2 ull {even,odd}
    ull*   w1p   = w0p + CPB / 2;
    ull*   w2p   = w1p + CPB / 2;
    float* cesh  = sh + NBUF * TILE_C * PADW + 3 * CPB;     // 32 floats

    const int t   = threadIdx.x;
    const int blk = blockIdx.x;
    const int b   = blk >> 3;
    const int s   = blk & 7;
    const int c0  = s * CPB;

    const int w    = t >> 5;       // warp = Gram group id
    const int lane = t & 31;
    const int cl4  = lane >> 3;    // channel-of-4
    const int u    = lane & 7;     // column pair (0..6 active)

    // weight gather: packed channel pairs (CPB/2 = 128 entries)
    if (t < CPB / 2) {
        const int i0 = idx[b * 3 + 0];
        const int i1 = idx[b * 3 + 1];
        const int i2 = idx[b * 3 + 2];
        const float* w0 = W + (size_t)i0 * NC;
        const float* w1 = W + (size_t)i1 * NC;
        const float* w2 = W + (size_t)i2 * NC;
        int c = c0 + 2 * t;
        w0p[t] = pk2(w0[c], w0[c + 1]);
        w1p[t] = pk2(w1[c], w1[c + 1]);
        w2p[t] = pk2(w2[c], w2[c + 1]);
    }

    const float* fbase = feat + ((size_t)b * NC + c0) * HW;

    // prime pipeline (prefetch distance 3, 5 buffers)
    prefetch_tile(fbase,                   tiles,                     t);
    asm volatile("cp.async.commit_group;\n");
    prefetch_tile(fbase +     TILE_C * HW, tiles +     TILE_C * PADW, t);
    asm volatile("cp.async.commit_group;\n");
    prefetch_tile(fbase + 2 * TILE_C * HW, tiles + 2 * TILE_C * PADW, t);
    asm volatile("cp.async.commit_group;\n");

    // ---- CE partial over classes [s*125, s*125+125) (overlaps prefetch) ----
    {
        const float* prow = pred + (size_t)b * NCLS + s * 125;
        float x = (t < 125) ? prow[t] : -1e30f;
        float m = x;
#pragma unroll
        for (int off = 16; off >= 1; off >>= 1)
            m = fmaxf(m, __shfl_xor_sync(0xffffffffu, m, off));
        if ((t & 31) == 0) cesh[t >> 5] = m;
        __syncthreads();
        float mx = cesh[0];
#pragma unroll
        for (int ww = 1; ww < 8; ww++) mx = fmaxf(mx, cesh[ww]);
        float e = (t < 125) ? expf(x - mx) : 0.0f;
#pragma unroll
        for (int off = 16; off >= 1; off >>= 1)
            e += __shfl_xor_sync(0xffffffffu, e, off);
        __syncthreads();
        if ((t & 31) == 0) cesh[8 + (t >> 5)] = e;
        __syncthreads();
        if (t == 0) {
            float sum = 0.f;
#pragma unroll
            for (int ww = 0; ww < 8; ww++) sum += cesh[8 + ww];
            g_cem[blk] = mx;
            g_ces[blk] = sum;
        }
    }

    ull acc[NACC];
#pragma unroll
    for (int i = 0; i < NACC; i++) acc[i] = 0ull;
    ull cam0a = 0ull, cam1a = 0ull, cam2a = 0ull, rsa = 0ull;
    const ull one2 = pk2(1.0f, 1.0f);

    int rdbuf = 0;
#pragma unroll 1
    for (int st = 0; st < NSTAGE; st++) {
        if (st + 3 < NSTAGE) {
            int wb = st + 3;
            int wbuf = wb - (wb / NBUF) * NBUF;
            prefetch_tile(fbase + (size_t)wb * TILE_C * HW,
                          tiles + wbuf * TILE_C * PADW, t);
            asm volatile("cp.async.commit_group;\n");
            asm volatile("cp.async.wait_group 3;\n");
        } else if (st + 2 < NSTAGE) {
            asm volatile("cp.async.wait_group 2;\n");
        } else if (st + 1 < NSTAGE) {
            asm volatile("cp.async.wait_group 1;\n");
        } else {
            asm volatile("cp.async.wait_group 0;\n");
        }
        __syncthreads();

        const float* buf = tiles + rdbuf * TILE_C * PADW;
        rdbuf = (rdbuf + 1 == NBUF) ? 0 : rdbuf + 1;

        // ---- Gram: 4 channels per thread, group (Q,S) from warp id ----
        if (u < 7) {
            const float* p0 = buf + cl4 * PADW + 2 * u;
#define GRAM4(QQ,SS) { gram_g<QQ,SS>(p0, acc); gram_g<QQ,SS>(p0 + 4*PADW, acc); \
                       gram_g<QQ,SS>(p0 + 8*PADW, acc); gram_g<QQ,SS>(p0 + 12*PADW, acc); }
            switch (w) {
                case 0: GRAM4(0,0); break;
                case 1: GRAM4(0,1); break;
                case 2: GRAM4(1,0); break;
                case 3: GRAM4(1,1); break;
                case 4: GRAM4(2,0); break;
                case 5: GRAM4(2,1); break;
                case 6: GRAM4(3,0); break;
                default: GRAM4(3,1); break;
            }
#undef GRAM4
        }

        // ---- CAM + rowsum: packed channel-pairs (8 per stage) ----
        if (t < HW) {
            const ull* wp0 = w0p + st * 8;
            const ull* wp1 = w1p + st * 8;
            const ull* wp2 = w2p + st * 8;
#pragma unroll
            for (int cc = 0; cc < 8; cc++) {
                float f0 = buf[(2 * cc) * PADW + t];
                float f1 = buf[(2 * cc + 1) * PADW + t];
                ull fp = pk2(f0, f1);
                cam0a = fma2(fp, wp0[cc], cam0a);
                cam1a = fma2(fp, wp1[cc], cam1a);
                cam2a = fma2(fp, wp2[cc], cam2a);
                rsa   = fma2(fp, one2,   rsa);
            }
        }
    }
    __syncthreads();   // all reads of last tile done before smem repurpose

    // ---- cam + rowsum outputs (fold channel-parity lanes) ----
    if (t < HW) {
        float a0, b0, a1, b1, a2, b2, ar, br;
        upk2(a0, b0, cam0a);
        upk2(a1, b1, cam1a);
        upk2(a2, b2, cam2a);
        upk2(ar, br, rsa);
        float* co = g_cam + (size_t)blk * 3 * HW;
        co[t]          = a0 + b0;
        co[HW + t]     = a1 + b1;
        co[2 * HW + t] = a2 + b2;
        sh[t] = ar + br;
    }
    __syncthreads();
    if (t < H) {
        float v = 0.f;
#pragma unroll
        for (int j = 0; j < H; j++) v += sh[t * H + j];
        g_rs[blk * H + t] = v;
    }
    __syncthreads();

    // ---- Gram dump: slab[t][NACC] ull (u=7 rows are zeros) ----
    ull* slab = (ull*)sh;                 // 256 x 15 ull = 30720 B
    {
        ull* d = slab + (size_t)t * NACC;
#pragma unroll
        for (int i = 0; i < NACC; i++) d[i] = acc[i];
    }
    __syncthreads();

    // ---- reducers: 105 threads fold 32 contributors, then fold lanes ----
    if (t < NPAIR) {
        int k = 0, rem = t;
        while (rem >= H - k) { rem -= H - k; k++; }
        int l = k + rem;
        int qq = (k & 1) * 2 + (l & 1);
        int a  = (k & 1) ? (k - 1) >> 1 : k >> 1;
        int b2 = (l & 1) ? (l - 1) >> 1 : l >> 1;
        int S  = (a < 2) ? 0 : 1;
        int ii;
        if (qq != 2) {
            if (S == 0) ii = (a == 0) ? b2 : 6 + b2;
            else {
                int la = a - 2, lb = b2 - 2;
                ii = la * 5 - (la * (la - 1)) / 2 + (lb - la);
            }
        } else {
            if (S == 0) ii = (a == 0) ? (b2 - 1) : 6 + (b2 - 2);
            else {
                int la = a - 2;
                ii = la * 4 - (la * (la - 1)) / 2 + (b2 - a - 1);
            }
        }
        const int g = qq * 2 + S;
        const ull* sp = slab + ((size_t)g * 32) * NACC + ii;
        ull v = 0ull;
#pragma unroll 8
        for (int rr = 0; rr < 32; rr++) v = add2(v, sp[(size_t)rr * NACC]);
        float aa, bb; upk2(aa, bb, v);
        g_G[(size_t)blk * NPAIR + t] = aa + bb;
    }
    __syncthreads();

    // ---- ticket: last block of this batch runs finalize ----
    __shared__ int sflag;
    if (t == 0) {
        __threadfence();
        int old = atomicAdd(&g_cnt_b[b], 1);
        sflag = (old == SPLITS - 1);
        if (old == SPLITS - 1) atomicExch(&g_cnt_b[b], 0);   // reset for replay
    }
    __syncthreads();
    if (!sflag) return;
    __threadfence();   // acquire other blocks' g_* writes

    // =================== finalize (per-batch) ===================
    float* camr = sh;               // 3*196
    float* D01s = sh + 588;
    float* D02s = sh + 784;
    float* dstb = sh + 980;
    float* Gs   = sh + 1176;
    float* rss  = sh + 1281;
    float* red  = sh + 1295;
    float* red2 = sh + 1551;
    float* bc   = sh + 1807;        // 8

    if (t < HW) {
#pragma unroll
        for (int j = 0; j < 3; j++) {
            float v = 0.f;
#pragma unroll
            for (int ss = 0; ss < SPLITS; ss++)
                v += g_cam[((size_t)(b * SPLITS + ss) * 3 + j) * HW + t];
            camr[j * HW + t] = v;
        }
    }
    if (t < NPAIR) {
        float v = 0.f;
#pragma unroll
        for (int ss = 0; ss < SPLITS; ss++) v += g_G[(size_t)(b * SPLITS + ss) * NPAIR + t];
        Gs[t] = v;
    }
    if (t < H) {
        float v = 0.f;
#pragma unroll
        for (int ss = 0; ss < SPLITS; ss++) v += g_rs[(b * SPLITS + ss) * H + t];
        rss[t] = v;
    }
    __syncthreads();

    if (t < 32) {
        float mn0 = 1e30f, mn1 = 1e30f, mn2 = 1e30f;
        float mx0 = -1e30f, mx1 = -1e30f, mx2 = -1e30f;
        for (int p = t; p < HW; p += 32) {
            float v0 = camr[p], v1 = camr[HW + p], v2 = camr[2 * HW + p];
            mn0 = fminf(mn0, v0); mx0 = fmaxf(mx0, v0);
            mn1 = fminf(mn1, v1); mx1 = fmaxf(mx1, v1);
            mn2 = fminf(mn2, v2); mx2 = fmaxf(mx2, v2);
        }
#pragma unroll
        for (int off = 16; off >= 1; off >>= 1) {
            mn0 = fminf(mn0, __shfl_xor_sync(0xffffffffu, mn0, off));
            mx0 = fmaxf(mx0, __shfl_xor_sync(0xffffffffu, mx0, off));
            mn1 = fminf(mn1, __shfl_xor_sync(0xffffffffu, mn1, off));
            mx1 = fmaxf(mx1, __shfl_xor_sync(0xffffffffu, mx1, off));
            mn2 = fminf(mn2, __shfl_xor_sync(0xffffffffu, mn2, off));
            mx2 = fmaxf(mx2, __shfl_xor_sync(0xffffffffu, mx2, off));
        }
        if (t == 0) {
            bc[0] = mn0; bc[1] = mn1; bc[2] = mn2;
            bc[3] = 255.f / (mx0 - mn0);
            bc[4] = 255.f / (mx1 - mn1);
            bc[5] = 255.f / (mx2 - mn2);
        }
    }
    __syncthreads();

    if (t < HW) {
        float v0 = (camr[t] - bc[0]) * bc[3];
        float v1 = (camr[HW + t] - bc[1]) * bc[4];
        float v2 = (camr[2 * HW + t] - bc[2]) * bc[5];
        D01s[t] = v0 - v1;
        D02s[t] = v0 - v2;
        dstb[t] = (v0 > THRV) ? 1.f : 0.f;
    }
    __syncthreads();

    float c01 = 0.f, c02 = 0.f;
    if (t < NPAIR) {
        int k = 0, rem = t;
        while (rem >= H - k) { rem -= H - k; k++; }
        int l = k + rem;
        float m01 = 0.f, m02 = 0.f;
#pragma unroll
        for (int i = 0; i < H; i++) {
            m01 = fmaf(D01s[i * H + k], D01s[i * H + l], m01);
            m02 = fmaf(D02s[i * H + k], D02s[i * H + l], m02);
        }
        float wgt = (k == l) ? 1.f : 2.f;
        c01 = wgt * m01 * Gs[t];
        c02 = wgt * m02 * Gs[t];
    }
    red[t]  = c01;
    red2[t] = c02;
    __syncthreads();
    if (t < 32) {
        float s1 = 0.f, s2 = 0.f;
        for (int p = t; p < NPAIR; p += 32) { s1 += red[p]; s2 += red2[p]; }
#pragma unroll
        for (int off = 16; off >= 1; off >>= 1) {
            s1 += __shfl_xor_sync(0xffffffffu, s1, off);
            s2 += __shfl_xor_sync(0xffffffffu, s2, off);
        }
        if (t == 0) { bc[6] = s1; bc[7] = s2; }
    }
    __syncthreads();

    if (t < H) {
        const float* srow = seg + (size_t)b * HW + t * H;
        float a = 0.f;
#pragma unroll
        for (int ww = 0; ww < H; ww++) {
            float d = dstb[t * H + ww] - srow[ww] + PD_EPS;
            a = fmaf(d, d, a);
        }
        red[t] = sqrtf(a);
    }
    __syncthreads();

    __shared__ int sflag2;
    if (t == 0) {
        float M = -1e30f;
#pragma unroll
        for (int ss = 0; ss < SPLITS; ss++) M = fmaxf(M, g_cem[b * SPLITS + ss]);
        float S = 0.f;
#pragma unroll
        for (int ss = 0; ss < SPLITS; ss++)
            S += g_ces[b * SPLITS + ss] * expf(g_cem[b * SPLITS + ss] - M);
        float ce = M + logf(S) - pred[(size_t)b * NCLS + cla[b]];

        float ed1 = 0.f;
#pragma unroll
        for (int hh = 0; hh < H; hh++) ed1 += red[hh];
        ed1 *= (1.f / H);

        float e01 = 0.f, e02 = 0.f;
#pragma unroll
        for (int k = 0; k < H; k++) {
            float s01 = 0.f, s02 = 0.f;
#pragma unroll
            for (int i = 0; i < H; i++) {
                s01 += D01s[i * H + k];
                s02 += D02s[i * H + k];
            }
            e01 = fmaf(s01, rss[k], e01);
            e02 = fmaf(s02, rss[k], e02);
        }
        const float epsq = PD_EPS * PD_EPS * (float)(HW * NC);
        float d01 = sqrtf(bc[6] + 2.f * PD_EPS * e01 + epsq) * (1.f / NC);
        float d02 = sqrtf(bc[7] + 2.f * PD_EPS * e02 + epsq) * (1.f / NC);
        g_r[b] = ed1 + fmaxf(MARGINV - d01 - d02, 0.f) + ce;

        __threadfence();
        int o2 = atomicAdd(&g_cnt_all, 1);
        sflag2 = (o2 == BZ - 1);
        if (o2 == BZ - 1) atomicExch(&g_cnt_all, 0);
    }
    __syncthreads();

    if (sflag2 && t == 0) {
        __threadfence();
        float v = 0.f;
#pragma unroll
        for (int i = 0; i < BZ; i++) v += g_r[i];
        out[0] = v * (1.f / BZ);
    }
}

// ---------------------------------------------------------------------------
extern "C" void kernel_launch(void* const* d_in, const int* in_sizes, int n_in,
                              void* d_out, int out_size) {
    const float* pred = (const float*)d_in[0];
    const int*   cla  = (const int*)  d_in[1];
    const float* seg  = (const float*)d_in[2];
    const float* feat = (const float*)d_in[3];
    const float* W    = (const float*)d_in[4];
    const int*   idx  = (const int*)  d_in[5];
    float* out = (float*)d_out;

    // tiles 5*16*208 (16640) + w 3*256 (768) + ce 32 = 17440 floats = 69760 B
    const int smem = (NBUF * TILE_C * PADW + 3 * CPB + 32) * (int)sizeof(float);
    cudaFuncSetAttribute(k1_fused, cudaFuncAttributeMaxDynamicSharedMemorySize, smem);

    k1_fused<<<BZ * SPLITS, TPB, smem>>>(feat, W, idx, pred, cla, seg, out);
}

// round 15
// speedup vs baseline: 1.1345x; 1.1345x over previous
#include <cuda_runtime.h>
#include <cstdint>

#define BZ     64
#define NC     2048
#define H      14
#define HW     196
#define NCLS   1000
#define MAXSPL 5
#define TILE_C 16
#define NBUF   5
#define TPB    256
#define PADW   208           // channel stride (words): conflict-free LDS.64
#define NPAIR  105
#define NACC   28
#define MARGINV 70.0f
#define THRV    125.0f
#define PD_EPS  1e-6f

typedef unsigned long long ull;

// scratch (device globals; no allocations allowed)
__device__ float g_G[BZ * MAXSPL * NPAIR];
__device__ float g_cam[BZ * MAXSPL * 3 * HW];
__device__ float g_rs[BZ * MAXSPL * H];
__device__ float g_cem[BZ * 4];
__device__ float g_ces[BZ * 4];
__device__ float g_r[BZ];
__device__ int   g_cnt_b[BZ];
__device__ int   g_cnt_all;

// ---------------- f32x2 helpers ----------------
__device__ __forceinline__ ull pk2(float lo, float hi) {
    ull r; asm("mov.b64 %0,{%1,%2};" : "=l"(r) : "f"(lo), "f"(hi)); return r;
}
__device__ __forceinline__ void upk2(float& lo, float& hi, ull v) {
    asm("mov.b64 {%0,%1},%2;" : "=f"(lo), "=f"(hi) : "l"(v));
}
__device__ __forceinline__ ull fma2(ull a, ull b, ull c) {
    ull d; asm("fma.rn.f32x2 %0,%1,%2,%3;" : "=l"(d) : "l"(a), "l"(b), "l"(c)); return d;
}
__device__ __forceinline__ ull add2(ull a, ull b) {
    ull d; asm("add.rn.f32x2 %0,%1,%2;" : "=l"(d) : "l"(a), "l"(b)); return d;
}

__device__ __forceinline__ constexpr int I0(int a, int b) {
    return a * 7 - (a * (a - 1)) / 2 + (b - a);          // 28 entries over 7 rows
}

// ---------------------------------------------------------------------------
// cp.async prefetch of one 16-channel tile into stride-PADW smem
// ---------------------------------------------------------------------------
__device__ __forceinline__ void prefetch_tile(const float* __restrict__ src_base,
                                              float* dst, int t) {
#pragma unroll
    for (int it = 0; it < 4; it++) {
        int q = t + it * TPB;            // 784 float4 transfers (16*49)
        if (q < TILE_C * 49) {
            int cc = q / 49;
            int p4 = q - cc * 49;
            const float* src = src_base + cc * HW + p4 * 4;
            unsigned dsts = (unsigned)__cvta_generic_to_shared(dst + cc * PADW + p4 * 4);
            asm volatile("cp.async.cg.shared.global [%0], [%1], 16;\n"
                         :: "r"(dsts), "l"(src));
        }
    }
}

// ---------------------------------------------------------------------------
// Gram 4-group split (row-contiguous LDS.64, 35 row-loads/channel total):
//   g0 low:    rows 0..6   x rows 0..6  (28 pairs, 7 loads)
//   g1 high:   rows 7..13  x rows 7..13 (28 pairs, 7 loads)
//   g2 crossA: rows 0..6   x rows 7..10 (28 pairs, 11 loads)
//   g3 crossB: rows 0..6   x rows 11..13(21 pairs, 10 loads)
// ---------------------------------------------------------------------------
template<int G>
__device__ __forceinline__ void gram_g(const float* __restrict__ p,
                                       ull* __restrict__ acc) {
    if (G == 0 || G == 1) {
        const int off = (G == 0) ? 0 : 98;     // rows 7..13 start at word 98
        ull r[7];
#pragma unroll
        for (int a = 0; a < 7; a++) r[a] = *(const ull*)(p + 14 * a + off);
#pragma unroll
        for (int a = 0; a < 7; a++)
#pragma unroll
            for (int b = a; b < 7; b++)
                acc[I0(a, b)] = fma2(r[a], r[b], acc[I0(a, b)]);
    } else if (G == 2) {
        ull rk[7], rl[4];
#pragma unroll
        for (int a = 0; a < 7; a++) rk[a] = *(const ull*)(p + 14 * a);
#pragma unroll
        for (int m = 0; m < 4; m++) rl[m] = *(const ull*)(p + 14 * (7 + m));
#pragma unroll
        for (int a = 0; a < 7; a++)
#pragma unroll
            for (int m = 0; m < 4; m++)
                acc[a * 4 + m] = fma2(rk[a], rl[m], acc[a * 4 + m]);
    } else {
        ull rk[7], rl[3];
#pragma unroll
        for (int a = 0; a < 7; a++) rk[a] = *(const ull*)(p + 14 * a);
#pragma unroll
        for (int m = 0; m < 3; m++) rl[m] = *(const ull*)(p + 14 * (11 + m));
#pragma unroll
        for (int a = 0; a < 7; a++)
#pragma unroll
            for (int m = 0; m < 3; m++)
                acc[a * 3 + m] = fma2(rk[a], rl[m], acc[a * 3 + m]);
    }
}

// ---------------------------------------------------------------------------
// Fused kernel: balanced 296-block grid + 4-group Gram + ticketed finalize
// bid layout: [0,96) 24 batches x 4 splits of 512ch (32 stages)
//             [96,136) batches 24..63, split0 = 512ch (32 stages)
//             [136,296) batches 24..63, splits 1..4 = 384ch (24 stages)
// ---------------------------------------------------------------------------
__global__ void __launch_bounds__(TPB, 2)
k1_fused(const float* __restrict__ feat,
         const float* __restrict__ W,
         const int*   __restrict__ idx,
         const float* __restrict__ pred,
         const int*   __restrict__ cla,
         const float* __restrict__ seg,
         float*       __restrict__ out) {
    extern __shared__ float sh[];
    float* tiles = sh;                                      // 5*16*208 = 16640 floats
    ull*   w0p   = (ull*)(sh + NBUF * TILE_C * PADW);       // 256 ull max
    ull*   w1p   = w0p + 256;
    ull*   w2p   = w1p + 256;
    float* cesh  = sh + NBUF * TILE_C * PADW + 3 * 512;     // 32 floats

    const int t   = threadIdx.x;
    const int bid = blockIdx.x;

    int b, c0, nst, sidx, cs;
    if (bid < 96)      { b = bid >> 2;        sidx = bid & 3; c0 = sidx * 512;      nst = 32; cs = sidx; }
    else if (bid < 136){ b = 24 + (bid - 96); sidx = 0;       c0 = 0;               nst = 32; cs = 0; }
    else { int j = bid - 136; int m = j & 3;
           b = 24 + (j >> 2);                 sidx = 1 + m;   c0 = 512 + m * 384;   nst = 24; cs = (m < 3) ? 1 + m : -1; }
    const int nspl = (b < 24) ? 4 : 5;
    const int cpb2 = nst * 8;      // (nst*16)/2 packed weight entries

    const int g    = t >> 6;       // Gram group (2 warps each)
    const int t64  = t & 63;
    const int cl8  = t64 >> 3;     // channel-of-8 (handles cl8, cl8+8)
    const int u    = t64 & 7;      // column pair (0..6 active)

    // weight gather: packed channel pairs
    if (t < cpb2) {
        const int i0 = idx[b * 3 + 0];
        const int i1 = idx[b * 3 + 1];
        const int i2 = idx[b * 3 + 2];
        const float* w0 = W + (size_t)i0 * NC;
        const float* w1 = W + (size_t)i1 * NC;
        const float* w2 = W + (size_t)i2 * NC;
        int c = c0 + 2 * t;
        w0p[t] = pk2(w0[c], w0[c + 1]);
        w1p[t] = pk2(w1[c], w1[c + 1]);
        w2p[t] = pk2(w2[c], w2[c + 1]);
    }

    const float* fbase = feat + ((size_t)b * NC + c0) * HW;

    // prime pipeline (prefetch distance 3, 5 buffers)
    prefetch_tile(fbase,                   tiles,                     t);
    asm volatile("cp.async.commit_group;\n");
    prefetch_tile(fbase +     TILE_C * HW, tiles +     TILE_C * PADW, t);
    asm volatile("cp.async.commit_group;\n");
    prefetch_tile(fbase + 2 * TILE_C * HW, tiles + 2 * TILE_C * PADW, t);
    asm volatile("cp.async.commit_group;\n");

    // ---- CE partial over classes [cs*250, cs*250+250) (block-uniform guard) ----
    if (cs >= 0) {
        const float* prow = pred + (size_t)b * NCLS + cs * 250;
        float x = (t < 250) ? prow[t] : -1e30f;
        float m = x;
#pragma unroll
        for (int off = 16; off >= 1; off >>= 1)
            m = fmaxf(m, __shfl_xor_sync(0xffffffffu, m, off));
        if ((t & 31) == 0) cesh[t >> 5] = m;
        __syncthreads();
        float mx = cesh[0];
#pragma unroll
        for (int ww = 1; ww < 8; ww++) mx = fmaxf(mx, cesh[ww]);
        float e = (t < 250) ? expf(x - mx) : 0.0f;
#pragma unroll
        for (int off = 16; off >= 1; off >>= 1)
            e += __shfl_xor_sync(0xffffffffu, e, off);
        __syncthreads();
        if ((t & 31) == 0) cesh[8 + (t >> 5)] = e;
        __syncthreads();
        if (t == 0) {
            float sum = 0.f;
#pragma unroll
            for (int ww = 0; ww < 8; ww++) sum += cesh[8 + ww];
            g_cem[b * 4 + cs] = mx;
            g_ces[b * 4 + cs] = sum;
        }
    }

    ull acc[NACC];
#pragma unroll
    for (int i = 0; i < NACC; i++) acc[i] = 0ull;
    ull cam0a = 0ull, cam1a = 0ull, cam2a = 0ull, rsa = 0ull;
    const ull one2 = pk2(1.0f, 1.0f);

    int rdbuf = 0;
#pragma unroll 1
    for (int st = 0; st < nst; st++) {
        if (st + 3 < nst) {
            int wb = st + 3;
            int wbuf = wb - (wb / NBUF) * NBUF;
            prefetch_tile(fbase + (size_t)wb * TILE_C * HW,
                          tiles + wbuf * TILE_C * PADW, t);
            asm volatile("cp.async.commit_group;\n");
            asm volatile("cp.async.wait_group 3;\n");
        } else if (st + 2 < nst) {
            asm volatile("cp.async.wait_group 2;\n");
        } else if (st + 1 < nst) {
            asm volatile("cp.async.wait_group 1;\n");
        } else {
            asm volatile("cp.async.wait_group 0;\n");
        }
        __syncthreads();

        const float* buf = tiles + rdbuf * TILE_C * PADW;
        rdbuf = (rdbuf + 1 == NBUF) ? 0 : rdbuf + 1;

        // ---- Gram: 2 channels per thread, group from warp pair ----
        if (u < 7) {
            const float* p0 = buf + cl8 * PADW + 2 * u;
            const float* p1 = p0 + 8 * PADW;
            if (g == 0)      { gram_g<0>(p0, acc); gram_g<0>(p1, acc); }
            else if (g == 1) { gram_g<1>(p0, acc); gram_g<1>(p1, acc); }
            else if (g == 2) { gram_g<2>(p0, acc); gram_g<2>(p1, acc); }
            else             { gram_g<3>(p0, acc); gram_g<3>(p1, acc); }
        }

        // ---- CAM + rowsum: packed channel-pairs (8 per stage) ----
        if (t < HW) {
            const ull* wp0 = w0p + st * 8;
            const ull* wp1 = w1p + st * 8;
            const ull* wp2 = w2p + st * 8;
#pragma unroll
            for (int cc = 0; cc < 8; cc++) {
                float f0 = buf[(2 * cc) * PADW + t];
                float f1 = buf[(2 * cc + 1) * PADW + t];
                ull fp = pk2(f0, f1);
                cam0a = fma2(fp, wp0[cc], cam0a);
                cam1a = fma2(fp, wp1[cc], cam1a);
                cam2a = fma2(fp, wp2[cc], cam2a);
                rsa   = fma2(fp, one2,   rsa);
            }
        }
    }
    __syncthreads();   // all reads of last tile done before smem repurpose

    const int slot = b * MAXSPL + sidx;

    // ---- cam + rowsum outputs (fold channel-parity lanes) ----
    if (t < HW) {
        float a0, b0, a1, b1, a2, b2, ar, br;
        upk2(a0, b0, cam0a);
        upk2(a1, b1, cam1a);
        upk2(a2, b2, cam2a);
        upk2(ar, br, rsa);
        float* co = g_cam + (size_t)slot * 3 * HW;
        co[t]          = a0 + b0;
        co[HW + t]     = a1 + b1;
        co[2 * HW + t] = a2 + b2;
        sh[t] = ar + br;
    }
    __syncthreads();
    if (t < H) {
        float v = 0.f;
#pragma unroll
        for (int j = 0; j < H; j++) v += sh[t * H + j];
        g_rs[slot * H + t] = v;
    }
    __syncthreads();

    // ---- Gram dump: slab[t][NACC] ull (u=7 rows are zeros) ----
    ull* slab = (ull*)sh;                 // 256 x 28 ull = 57344 B
    {
        ull* d = slab + (size_t)t * NACC;
#pragma unroll
        for (int i = 0; i < NACC; i++) d[i] = acc[i];
    }
    __syncthreads();

    // ---- reducers: 105 threads fold 64 contributors, then fold lanes ----
    if (t < NPAIR) {
        int k = 0, rem = t;
        while (rem >= H - k) { rem -= H - k; k++; }
        int l = k + rem;
        int gg, ii;
        if (l <= 6)       { gg = 0; ii = I0(k, l); }
        else if (k >= 7)  { gg = 1; ii = I0(k - 7, l - 7); }
        else if (l <= 10) { gg = 2; ii = k * 4 + (l - 7); }
        else              { gg = 3; ii = k * 3 + (l - 11); }
        const ull* sp = slab + ((size_t)gg * 64) * NACC + ii;
        ull v = 0ull;
#pragma unroll 8
        for (int rr = 0; rr < 64; rr++) v = add2(v, sp[(size_t)rr * NACC]);
        float aa, bb; upk2(aa, bb, v);
        g_G[(size_t)slot * NPAIR + t] = aa + bb;
    }
    __syncthreads();

    // ---- ticket: last block of this batch runs finalize ----
    __shared__ int sflag;
    if (t == 0) {
        __threadfence();
        int old = atomicAdd(&g_cnt_b[b], 1);
        sflag = (old == nspl - 1);
        if (old == nspl - 1) atomicExch(&g_cnt_b[b], 0);   // reset for replay
    }
    __syncthreads();
    if (!sflag) return;
    __threadfence();   // acquire other blocks' g_* writes

    // =================== finalize (per-batch) ===================
    float* camr = sh;               // 3*196
    float* D01s = sh + 588;
    float* D02s = sh + 784;
    float* dstb = sh + 980;
    float* Gs   = sh + 1176;
    float* rss  = sh + 1281;
    float* red  = sh + 1295;
    float* red2 = sh + 1551;
    float* bc   = sh + 1807;        // 8

    if (t < HW) {
#pragma unroll
        for (int j = 0; j < 3; j++) {
            float v = 0.f;
            for (int ss = 0; ss < nspl; ss++)
                v += g_cam[((size_t)(b * MAXSPL + ss) * 3 + j) * HW + t];
            camr[j * HW + t] = v;
        }
    }
    if (t < NPAIR) {
        float v = 0.f;
        for (int ss = 0; ss < nspl; ss++) v += g_G[(size_t)(b * MAXSPL + ss) * NPAIR + t];
        Gs[t] = v;
    }
    if (t < H) {
        float v = 0.f;
        for (int ss = 0; ss < nspl; ss++) v += g_rs[(b * MAXSPL + ss) * H + t];
        rss[t] = v;
    }
    __syncthreads();

    if (t < 32) {
        float mn0 = 1e30f, mn1 = 1e30f, mn2 = 1e30f;
        float mx0 = -1e30f, mx1 = -1e30f, mx2 = -1e30f;
        for (int p = t; p < HW; p += 32) {
            float v0 = camr[p], v1 = camr[HW + p], v2 = camr[2 * HW + p];
            mn0 = fminf(mn0, v0); mx0 = fmaxf(mx0, v0);
            mn1 = fminf(mn1, v1); mx1 = fmaxf(mx1, v1);
            mn2 = fminf(mn2, v2); mx2 = fmaxf(mx2, v2);
        }
#pragma unroll
        for (int off = 16; off >= 1; off >>= 1) {
            mn0 = fminf(mn0, __shfl_xor_sync(0xffffffffu, mn0, off));
            mx0 = fmaxf(mx0, __shfl_xor_sync(0xffffffffu, mx0, off));
            mn1 = fminf(mn1, __shfl_xor_sync(0xffffffffu, mn1, off));
            mx1 = fmaxf(mx1, __shfl_xor_sync(0xffffffffu, mx1, off));
            mn2 = fminf(mn2, __shfl_xor_sync(0xffffffffu, mn2, off));
            mx2 = fmaxf(mx2, __shfl_xor_sync(0xffffffffu, mx2, off));
        }
        if (t == 0) {
            bc[0] = mn0; bc[1] = mn1; bc[2] = mn2;
            bc[3] = 255.f / (mx0 - mn0);
            bc[4] = 255.f / (mx1 - mn1);
            bc[5] = 255.f / (mx2 - mn2);
        }
    }
    __syncthreads();

    if (t < HW) {
        float v0 = (camr[t] - bc[0]) * bc[3];
        float v1 = (camr[HW + t] - bc[1]) * bc[4];
        float v2 = (camr[2 * HW + t] - bc[2]) * bc[5];
        D01s[t] = v0 - v1;
        D02s[t] = v0 - v2;
        dstb[t] = (v0 > THRV) ? 1.f : 0.f;
    }
    __syncthreads();

    float c01 = 0.f, c02 = 0.f;
    if (t < NPAIR) {
        int k = 0, rem = t;
        while (rem >= H - k) { rem -= H - k; k++; }
        int l = k + rem;
        float m01 = 0.f, m02 = 0.f;
#pragma unroll
        for (int i = 0; i < H; i++) {
            m01 = fmaf(D01s[i * H + k], D01s[i * H + l], m01);
            m02 = fmaf(D02s[i * H + k], D02s[i * H + l], m02);
        }
        float wgt = (k == l) ? 1.f : 2.f;
        c01 = wgt * m01 * Gs[t];
        c02 = wgt * m02 * Gs[t];
    }
    red[t]  = c01;
    red2[t] = c02;
    __syncthreads();
    if (t < 32) {
        float s1 = 0.f, s2 = 0.f;
        for (int p = t; p < NPAIR; p += 32) { s1 += red[p]; s2 += red2[p]; }
#pragma unroll
        for (int off = 16; off >= 1; off >>= 1) {
            s1 += __shfl_xor_sync(0xffffffffu, s1, off);
            s2 += __shfl_xor_sync(0xffffffffu, s2, off);
        }
        if (t == 0) { bc[6] = s1; bc[7] = s2; }
    }
    __syncthreads();

    if (t < H) {
        const float* srow = seg + (size_t)b * HW + t * H;
        float a = 0.f;
#pragma unroll
        for (int ww = 0; ww < H; ww++) {
            float d = dstb[t * H + ww] - srow[ww] + PD_EPS;
            a = fmaf(d, d, a);
        }
        red[t] = sqrtf(a);
    }
    __syncthreads();

    __shared__ int sflag2;
    if (t == 0) {
        float m0 = g_cem[b * 4 + 0], m1 = g_cem[b * 4 + 1];
        float m2 = g_cem[b * 4 + 2], m3 = g_cem[b * 4 + 3];
        float M = fmaxf(fmaxf(m0, m1), fmaxf(m2, m3));
        float S = g_ces[b * 4 + 0] * expf(m0 - M) + g_ces[b * 4 + 1] * expf(m1 - M)
                + g_ces[b * 4 + 2] * expf(m2 - M) + g_ces[b * 4 + 3] * expf(m3 - M);
        float ce = M + logf(S) - pred[(size_t)b * NCLS + cla[b]];

        float ed1 = 0.f;
#pragma unroll
        for (int hh = 0; hh < H; hh++) ed1 += red[hh];
        ed1 *= (1.f / H);

        float e01 = 0.f, e02 = 0.f;
#pragma unroll
        for (int k = 0; k < H; k++) {
            float s01 = 0.f, s02 = 0.f;
#pragma unroll
            for (int i = 0; i < H; i++) {
                s01 += D01s[i * H + k];
                s02 += D02s[i * H + k];
            }
            e01 = fmaf(s01, rss[k], e01);
            e02 = fmaf(s02, rss[k], e02);
        }
        const float epsq = PD_EPS * PD_EPS * (float)(HW * NC);
        float d01 = sqrtf(bc[6] + 2.f * PD_EPS * e01 + epsq) * (1.f / NC);
        float d02 = sqrtf(bc[7] + 2.f * PD_EPS * e02 + epsq) * (1.f / NC);
        g_r[b] = ed1 + fmaxf(MARGINV - d01 - d02, 0.f) + ce;

        __threadfence();
        int o2 = atomicAdd(&g_cnt_all, 1);
        sflag2 = (o2 == BZ - 1);
        if (o2 == BZ - 1) atomicExch(&g_cnt_all, 0);
    }
    __syncthreads();

    if (sflag2 && t == 0) {
        __threadfence();
        float v = 0.f;
#pragma unroll
        for (int i = 0; i < BZ; i++) v += g_r[i];
        out[0] = v * (1.f / BZ);
    }
}

// ---------------------------------------------------------------------------
extern "C" void kernel_launch(void* const* d_in, const int* in_sizes, int n_in,
                              void* d_out, int out_size) {
    const float* pred = (const float*)d_in[0];
    const int*   cla  = (const int*)  d_in[1];
    const float* seg  = (const float*)d_in[2];
    const float* feat = (const float*)d_in[3];
    const float* W    = (const float*)d_in[4];
    const int*   idx  = (const int*)  d_in[5];
    float* out = (float*)d_out;

    // tiles 5*16*208 (16640) + w 3*512 (1536) + ce 32 = 18208 floats = 72832 B
    const int smem = (NBUF * TILE_C * PADW + 3 * 512 + 32) * (int)sizeof(float);
    cudaFuncSetAttribute(k1_fused, cudaFuncAttributeMaxDynamicSharedMemorySize, smem);

    k1_fused<<<296, TPB, smem>>>(feat, W, idx, pred, cla, seg, out);
}

// round 16
// speedup vs baseline: 1.1608x; 1.0232x over previous
#include <cuda_runtime.h>
#include <cstdint>

#define BZ     64
#define NC     2048
#define H      14
#define HW     196
#define NCLS   1000
#define SPLITS 4
#define CPB    512
#define TILE_C 16
#define NSTAGE 32            // CPB / TILE_C
#define NBUF   5
#define TPB    256
#define PADW   208           // channel stride (words): conflict-free LDS.64
#define NPAIR  105
#define NACC   28
#define MARGINV 70.0f
#define THRV    125.0f
#define PD_EPS  1e-6f

typedef unsigned long long ull;

// scratch (device globals; no allocations allowed)
__device__ float g_G[BZ * SPLITS * NPAIR];
__device__ float g_cam[BZ * SPLITS * 3 * HW];
__device__ float g_rs[BZ * SPLITS * H];
__device__ float g_cem[BZ * SPLITS];
__device__ float g_ces[BZ * SPLITS];
__device__ float g_r[BZ];
__device__ int   g_cnt_b[BZ];
__device__ int   g_cnt_all;

// ---------------- f32x2 helpers ----------------
__device__ __forceinline__ ull pk2(float lo, float hi) {
    ull r; asm("mov.b64 %0,{%1,%2};" : "=l"(r) : "f"(lo), "f"(hi)); return r;
}
__device__ __forceinline__ void upk2(float& lo, float& hi, ull v) {
    asm("mov.b64 {%0,%1},%2;" : "=f"(lo), "=f"(hi) : "l"(v));
}
__device__ __forceinline__ ull fma2(ull a, ull b, ull c) {
    ull d; asm("fma.rn.f32x2 %0,%1,%2,%3;" : "=l"(d) : "l"(a), "l"(b), "l"(c)); return d;
}
__device__ __forceinline__ ull add2(ull a, ull b) {
    ull d; asm("add.rn.f32x2 %0,%1,%2;" : "=l"(d) : "l"(a), "l"(b)); return d;
}

__device__ __forceinline__ constexpr int I0(int a, int b) {
    return a * 7 - (a * (a - 1)) / 2 + (b - a);          // 28 entries over 7 rows
}

// ---------------------------------------------------------------------------
// cp.async prefetch of one 16-channel tile into stride-PADW smem
// ---------------------------------------------------------------------------
__device__ __forceinline__ void prefetch_tile(const float* __restrict__ src_base,
                                              float* dst, int t) {
#pragma unroll
    for (int it = 0; it < 4; it++) {
        int q = t + it * TPB;            // 784 float4 transfers (16*49)
        if (q < TILE_C * 49) {
            int cc = q / 49;
            int p4 = q - cc * 49;
            const float* src = src_base + cc * HW + p4 * 4;
            unsigned dsts = (unsigned)__cvta_generic_to_shared(dst + cc * PADW + p4 * 4);
            asm volatile("cp.async.cg.shared.global [%0], [%1], 16;\n"
                         :: "r"(dsts), "l"(src));
        }
    }
}

// ---------------------------------------------------------------------------
// Gram 4-group split (row-contiguous LDS.64, 35 row-loads/channel total):
//   g0 low:    rows 0..6   x rows 0..6   (28 pairs, 7 loads)
//   g1 high:   rows 7..13  x rows 7..13  (28 pairs, 7 loads)
//   g2 crossA: rows 0..6   x rows 7..10  (28 pairs, 11 loads)
//   g3 crossB: rows 0..6   x rows 11..13 (21 pairs, 10 loads)
// ---------------------------------------------------------------------------
template<int G>
__device__ __forceinline__ void gram_g(const float* __restrict__ p,
                                       ull* __restrict__ acc) {
    if (G == 0 || G == 1) {
        const int off = (G == 0) ? 0 : 98;     // rows 7..13 start at word 98
        ull r[7];
#pragma unroll
        for (int a = 0; a < 7; a++) r[a] = *(const ull*)(p + 14 * a + off);
#pragma unroll
        for (int a = 0; a < 7; a++)
#pragma unroll
            for (int b = a; b < 7; b++)
                acc[I0(a, b)] = fma2(r[a], r[b], acc[I0(a, b)]);
    } else if (G == 2) {
        ull rk[7], rl[4];
#pragma unroll
        for (int a = 0; a < 7; a++) rk[a] = *(const ull*)(p + 14 * a);
#pragma unroll
        for (int m = 0; m < 4; m++) rl[m] = *(const ull*)(p + 14 * (7 + m));
#pragma unroll
        for (int a = 0; a < 7; a++)
#pragma unroll
            for (int m = 0; m < 4; m++)
                acc[a * 4 + m] = fma2(rk[a], rl[m], acc[a * 4 + m]);
    } else {
        ull rk[7], rl[3];
#pragma unroll
        for (int a = 0; a < 7; a++) rk[a] = *(const ull*)(p + 14 * a);
#pragma unroll
        for (int m = 0; m < 3; m++) rl[m] = *(const ull*)(p + 14 * (11 + m));
#pragma unroll
        for (int a = 0; a < 7; a++)
#pragma unroll
            for (int m = 0; m < 3; m++)
                acc[a * 3 + m] = fma2(rk[a], rl[m], acc[a * 3 + m]);
    }
}

// ---------------------------------------------------------------------------
// Fused kernel: 4-group Gram + pixel-pair CAM + ticketed finalize
// ---------------------------------------------------------------------------
__global__ void __launch_bounds__(TPB, 2)
k1_fused(const float* __restrict__ feat,
         const float* __restrict__ W,
         const int*   __restrict__ idx,
         const float* __restrict__ pred,
         const int*   __restrict__ cla,
         const float* __restrict__ seg,
         float*       __restrict__ out) {
    extern __shared__ float sh[];
    float* tiles = sh;                                      // 5*16*208 = 16640 floats
    ull*   wb0   = (ull*)(sh + NBUF * TILE_C * PADW);       // 512 ull {w,w} broadcast
    ull*   wb1   = wb0 + CPB;
    ull*   wb2   = wb1 + CPB;
    float* cesh  = sh + NBUF * TILE_C * PADW + 6 * CPB;     // 32 floats

    const int t   = threadIdx.x;
    const int blk = blockIdx.x;
    const int b   = blk >> 2;
    const int s   = blk & 3;
    const int c0  = s * CPB;

    const int g    = t >> 6;       // Gram group (2 warps each)
    const int t64  = t & 63;
    const int cl8  = t64 >> 3;     // channel-of-8 (handles cl8, cl8+8)
    const int u    = t64 & 7;      // column pair (0..6 active)

    // CAM role: thread t<196 -> pixel pair qp = t%98, channel half = t/98
    const int qp   = (t < 98) ? t : t - 98;
    const int chh  = (t < 98) ? 0 : 1;     // channel half (0: ch 0-7, 1: ch 8-15)

    // weight gather: broadcast-packed {w,w}
    {
        const int i0 = idx[b * 3 + 0];
        const int i1 = idx[b * 3 + 1];
        const int i2 = idx[b * 3 + 2];
        const float* w0 = W + (size_t)i0 * NC;
        const float* w1 = W + (size_t)i1 * NC;
        const float* w2 = W + (size_t)i2 * NC;
#pragma unroll
        for (int cc = t; cc < CPB; cc += TPB) {
            int c = c0 + cc;
            float a0 = w0[c], a1 = w1[c], a2 = w2[c];
            wb0[cc] = pk2(a0, a0);
            wb1[cc] = pk2(a1, a1);
            wb2[cc] = pk2(a2, a2);
        }
    }

    const float* fbase = feat + ((size_t)b * NC + c0) * HW;

    // prime pipeline (prefetch distance 3, 5 buffers)
    prefetch_tile(fbase,                   tiles,                     t);
    asm volatile("cp.async.commit_group;\n");
    prefetch_tile(fbase +     TILE_C * HW, tiles +     TILE_C * PADW, t);
    asm volatile("cp.async.commit_group;\n");
    prefetch_tile(fbase + 2 * TILE_C * HW, tiles + 2 * TILE_C * PADW, t);
    asm volatile("cp.async.commit_group;\n");

    // ---- CE partial over classes [s*250, s*250+250) (overlaps prefetch) ----
    {
        const float* prow = pred + (size_t)b * NCLS + s * 250;
        float x = (t < 250) ? prow[t] : -1e30f;
        float m = x;
#pragma unroll
        for (int off = 16; off >= 1; off >>= 1)
            m = fmaxf(m, __shfl_xor_sync(0xffffffffu, m, off));
        if ((t & 31) == 0) cesh[t >> 5] = m;
        __syncthreads();
        float mx = cesh[0];
#pragma unroll
        for (int ww = 1; ww < 8; ww++) mx = fmaxf(mx, cesh[ww]);
        float e = (t < 250) ? expf(x - mx) : 0.0f;
#pragma unroll
        for (int off = 16; off >= 1; off >>= 1)
            e += __shfl_xor_sync(0xffffffffu, e, off);
        __syncthreads();
        if ((t & 31) == 0) cesh[8 + (t >> 5)] = e;
        __syncthreads();
        if (t == 0) {
            float sum = 0.f;
#pragma unroll
            for (int ww = 0; ww < 8; ww++) sum += cesh[8 + ww];
            g_cem[blk] = mx;
            g_ces[blk] = sum;
        }
    }

    ull acc[NACC];
#pragma unroll
    for (int i = 0; i < NACC; i++) acc[i] = 0ull;
    ull cam0a = 0ull, cam1a = 0ull, cam2a = 0ull, rsa = 0ull;

    int rdbuf = 0;
#pragma unroll 1
    for (int st = 0; st < NSTAGE; st++) {
        if (st + 3 < NSTAGE) {
            int wb = st + 3;
            int wbuf = wb - (wb / NBUF) * NBUF;
            prefetch_tile(fbase + (size_t)wb * TILE_C * HW,
                          tiles + wbuf * TILE_C * PADW, t);
            asm volatile("cp.async.commit_group;\n");
            asm volatile("cp.async.wait_group 3;\n");
        } else if (st + 2 < NSTAGE) {
            asm volatile("cp.async.wait_group 2;\n");
        } else if (st + 1 < NSTAGE) {
            asm volatile("cp.async.wait_group 1;\n");
        } else {
            asm volatile("cp.async.wait_group 0;\n");
        }
        __syncthreads();

        const float* buf = tiles + rdbuf * TILE_C * PADW;
        rdbuf = (rdbuf + 1 == NBUF) ? 0 : rdbuf + 1;

        // ---- Gram: 2 channels per thread, group from warp pair ----
        if (u < 7) {
            const float* p0 = buf + cl8 * PADW + 2 * u;
            const float* p1 = p0 + 8 * PADW;
            if (g == 0)      { gram_g<0>(p0, acc); gram_g<0>(p1, acc); }
            else if (g == 1) { gram_g<1>(p0, acc); gram_g<1>(p1, acc); }
            else if (g == 2) { gram_g<2>(p0, acc); gram_g<2>(p1, acc); }
            else             { gram_g<3>(p0, acc); gram_g<3>(p1, acc); }
        }

        // ---- CAM + rowsum: pixel-pair LDS.64, channel-half split ----
        if (t < HW) {
            const ull* wp0 = wb0 + st * TILE_C + chh * 8;
            const ull* wp1 = wb1 + st * TILE_C + chh * 8;
            const ull* wp2 = wb2 + st * TILE_C + chh * 8;
            const float* pbase = buf + chh * 8 * PADW + 2 * qp;
#pragma unroll
            for (int cc = 0; cc < 8; cc++) {
                ull fp = *(const ull*)(pbase + cc * PADW);
                cam0a = fma2(fp, wp0[cc], cam0a);
                cam1a = fma2(fp, wp1[cc], cam1a);
                cam2a = fma2(fp, wp2[cc], cam2a);
                rsa   = add2(rsa, fp);
            }
        }
    }
    __syncthreads();   // all reads of last tile done before smem repurpose

    // ---- CAM fold across channel halves (lanes = pixels 2qp, 2qp+1) ----
    {
        ull* fold = (ull*)sh;               // 98 x 4 ull = 3136 B
        if (t >= 98 && t < HW) {
            ull* d = fold + (size_t)qp * 4;
            d[0] = cam0a; d[1] = cam1a; d[2] = cam2a; d[3] = rsa;
        }
        __syncthreads();
        if (t < 98) {
            const ull* d = fold + (size_t)qp * 4;
            cam0a = add2(cam0a, d[0]);
            cam1a = add2(cam1a, d[1]);
            cam2a = add2(cam2a, d[2]);
            rsa   = add2(rsa,   d[3]);
        }
        __syncthreads();
        if (t < 98) {
            float a0, b0, a1, b1, a2, b2, ar, br;
            upk2(a0, b0, cam0a);
            upk2(a1, b1, cam1a);
            upk2(a2, b2, cam2a);
            upk2(ar, br, rsa);
            float* co = g_cam + (size_t)blk * 3 * HW;
            co[2 * qp]              = a0;  co[2 * qp + 1]          = b0;
            co[HW + 2 * qp]         = a1;  co[HW + 2 * qp + 1]     = b1;
            co[2 * HW + 2 * qp]     = a2;  co[2 * HW + 2 * qp + 1] = b2;
            sh[2 * qp] = ar;  sh[2 * qp + 1] = br;
        }
    }
    __syncthreads();
    if (t < H) {
        float v = 0.f;
#pragma unroll
        for (int j = 0; j < H; j++) v += sh[t * H + j];
        g_rs[blk * H + t] = v;
    }
    __syncthreads();

    // ---- Gram dump: slab[t][NACC] ull (u=7 rows are zeros) ----
    ull* slab = (ull*)sh;                 // 256 x 28 ull = 57344 B
    {
        ull* d = slab + (size_t)t * NACC;
#pragma unroll
        for (int i = 0; i < NACC; i++) d[i] = acc[i];
    }
    __syncthreads();

    // ---- reducers: 105 threads fold 64 contributors, then fold lanes ----
    if (t < NPAIR) {
        int k = 0, rem = t;
        while (rem >= H - k) { rem -= H - k; k++; }
        int l = k + rem;
        int gg, ii;
        if (l <= 6)       { gg = 0; ii = I0(k, l); }
        else if (k >= 7)  { gg = 1; ii = I0(k - 7, l - 7); }
        else if (l <= 10) { gg = 2; ii = k * 4 + (l - 7); }
        else              { gg = 3; ii = k * 3 + (l - 11); }
        const ull* sp = slab + ((size_t)gg * 64) * NACC + ii;
        ull v = 0ull;
#pragma unroll 8
        for (int rr = 0; rr < 64; rr++) v = add2(v, sp[(size_t)rr * NACC]);
        float aa, bb; upk2(aa, bb, v);
        g_G[(size_t)blk * NPAIR + t] = aa + bb;
    }
    __syncthreads();

    // ---- ticket: last block of this batch runs finalize ----
    __shared__ int sflag;
    if (t == 0) {
        __threadfence();
        int old = atomicAdd(&g_cnt_b[b], 1);
        sflag = (old == SPLITS - 1);
        if (old == SPLITS - 1) atomicExch(&g_cnt_b[b], 0);   // reset for replay
    }
    __syncthreads();
    if (!sflag) return;
    __threadfence();   // acquire other blocks' g_* writes

    // =================== finalize (per-batch) ===================
    float* camr = sh;               // 3*196
    float* D01s = sh + 588;
    float* D02s = sh + 784;
    float* dstb = sh + 980;
    float* Gs   = sh + 1176;
    float* rss  = sh + 1281;
    float* red  = sh + 1295;
    float* red2 = sh + 1551;
    float* bc   = sh + 1807;        // 8

    if (t < HW) {
#pragma unroll
        for (int j = 0; j < 3; j++) {
            float v = 0.f;
#pragma unroll
            for (int ss = 0; ss < SPLITS; ss++)
                v += g_cam[((size_t)(b * SPLITS + ss) * 3 + j) * HW + t];
            camr[j * HW + t] = v;
        }
    }
    if (t < NPAIR) {
        float v = 0.f;
#pragma unroll
        for (int ss = 0; ss < SPLITS; ss++) v += g_G[(size_t)(b * SPLITS + ss) * NPAIR + t];
        Gs[t] = v;
    }
    if (t < H) {
        float v = 0.f;
#pragma unroll
        for (int ss = 0; ss < SPLITS; ss++) v += g_rs[(b * SPLITS + ss) * H + t];
        rss[t] = v;
    }
    __syncthreads();

    if (t < 32) {
        float mn0 = 1e30f, mn1 = 1e30f, mn2 = 1e30f;
        float mx0 = -1e30f, mx1 = -1e30f, mx2 = -1e30f;
        for (int p = t; p < HW; p += 32) {
            float v0 = camr[p], v1 = camr[HW + p], v2 = camr[2 * HW + p];
            mn0 = fminf(mn0, v0); mx0 = fmaxf(mx0, v0);
            mn1 = fminf(mn1, v1); mx1 = fmaxf(mx1, v1);
            mn2 = fminf(mn2, v2); mx2 = fmaxf(mx2, v2);
        }
#pragma unroll
        for (int off = 16; off >= 1; off >>= 1) {
            mn0 = fminf(mn0, __shfl_xor_sync(0xffffffffu, mn0, off));
            mx0 = fmaxf(mx0, __shfl_xor_sync(0xffffffffu, mx0, off));
            mn1 = fminf(mn1, __shfl_xor_sync(0xffffffffu, mn1, off));
            mx1 = fmaxf(mx1, __shfl_xor_sync(0xffffffffu, mx1, off));
            mn2 = fminf(mn2, __shfl_xor_sync(0xffffffffu, mn2, off));
            mx2 = fmaxf(mx2, __shfl_xor_sync(0xffffffffu, mx2, off));
        }
        if (t == 0) {
            bc[0] = mn0; bc[1] = mn1; bc[2] = mn2;
            bc[3] = 255.f / (mx0 - mn0);
            bc[4] = 255.f / (mx1 - mn1);
            bc[5] = 255.f / (mx2 - mn2);
        }
    }
    __syncthreads();

    if (t < HW) {
        float v0 = (camr[t] - bc[0]) * bc[3];
        float v1 = (camr[HW + t] - bc[1]) * bc[4];
        float v2 = (camr[2 * HW + t] - bc[2]) * bc[5];
        D01s[t] = v0 - v1;
        D02s[t] = v0 - v2;
        dstb[t] = (v0 > THRV) ? 1.f : 0.f;
    }
    __syncthreads();

    float c01 = 0.f, c02 = 0.f;
    if (t < NPAIR) {
        int k = 0, rem = t;
        while (rem >= H - k) { rem -= H - k; k++; }
        int l = k + rem;
        float m01 = 0.f, m02 = 0.f;
#pragma unroll
        for (int i = 0; i < H; i++) {
            m01 = fmaf(D01s[i * H + k], D01s[i * H + l], m01);
            m02 = fmaf(D02s[i * H + k], D02s[i * H + l], m02);
        }
        float wgt = (k == l) ? 1.f : 2.f;
        c01 = wgt * m01 * Gs[t];
        c02 = wgt * m02 * Gs[t];
    }
    red[t]  = c01;
    red2[t] = c02;
    __syncthreads();
    if (t < 32) {
        float s1 = 0.f, s2 = 0.f;
        for (int p = t; p < NPAIR; p += 32) { s1 += red[p]; s2 += red2[p]; }
#pragma unroll
        for (int off = 16; off >= 1; off >>= 1) {
            s1 += __shfl_xor_sync(0xffffffffu, s1, off);
            s2 += __shfl_xor_sync(0xffffffffu, s2, off);
        }
        if (t == 0) { bc[6] = s1; bc[7] = s2; }
    }
    __syncthreads();

    if (t < H) {
        const float* srow = seg + (size_t)b * HW + t * H;
        float a = 0.f;
#pragma unroll
        for (int ww = 0; ww < H; ww++) {
            float d = dstb[t * H + ww] - srow[ww] + PD_EPS;
            a = fmaf(d, d, a);
        }
        red[t] = sqrtf(a);
    }
    __syncthreads();

    __shared__ int sflag2;
    if (t == 0) {
        float m0 = g_cem[b * 4 + 0], m1 = g_cem[b * 4 + 1];
        float m2 = g_cem[b * 4 + 2], m3 = g_cem[b * 4 + 3];
        float M = fmaxf(fmaxf(m0, m1), fmaxf(m2, m3));
        float S = g_ces[b * 4 + 0] * expf(m0 - M) + g_ces[b * 4 + 1] * expf(m1 - M)
                + g_ces[b * 4 + 2] * expf(m2 - M) + g_ces[b * 4 + 3] * expf(m3 - M);
        float ce = M + logf(S) - pred[(size_t)b * NCLS + cla[b]];

        float ed1 = 0.f;
#pragma unroll
        for (int hh = 0; hh < H; hh++) ed1 += red[hh];
        ed1 *= (1.f / H);

        float e01 = 0.f, e02 = 0.f;
#pragma unroll
        for (int k = 0; k < H; k++) {
            float s01 = 0.f, s02 = 0.f;
#pragma unroll
            for (int i = 0; i < H; i++) {
                s01 += D01s[i * H + k];
                s02 += D02s[i * H + k];
            }
            e01 = fmaf(s01, rss[k], e01);
            e02 = fmaf(s02, rss[k], e02);
        }
        const float epsq = PD_EPS * PD_EPS * (float)(HW * NC);
        float d01 = sqrtf(bc[6] + 2.f * PD_EPS * e01 + epsq) * (1.f / NC);
        float d02 = sqrtf(bc[7] + 2.f * PD_EPS * e02 + epsq) * (1.f / NC);
        g_r[b] = ed1 + fmaxf(MARGINV - d01 - d02, 0.f) + ce;

        __threadfence();
        int o2 = atomicAdd(&g_cnt_all, 1);
        sflag2 = (o2 == BZ - 1);
        if (o2 == BZ - 1) atomicExch(&g_cnt_all, 0);
    }
    __syncthreads();

    if (sflag2 && t == 0) {
        __threadfence();
        float v = 0.f;
#pragma unroll
        for (int i = 0; i < BZ; i++) v += g_r[i];
        out[0] = v * (1.f / BZ);
    }
}

// ---------------------------------------------------------------------------
extern "C" void kernel_launch(void* const* d_in, const int* in_sizes, int n_in,
                              void* d_out, int out_size) {
    const float* pred = (const float*)d_in[0];
    const int*   cla  = (const int*)  d_in[1];
    const float* seg  = (const float*)d_in[2];
    const float* feat = (const float*)d_in[3];
    const float* W    = (const float*)d_in[4];
    const int*   idx  = (const int*)  d_in[5];
    float* out = (float*)d_out;

    // tiles 5*16*208 (16640) + wb 3*1024 (3072) + ce 32 = 19744 floats = 78976 B
    const int smem = (NBUF * TILE_C * PADW + 6 * CPB + 32) * (int)sizeof(float);
    cudaFuncSetAttribute(k1_fused, cudaFuncAttributeMaxDynamicSharedMemorySize, smem);

    k1_fused<<<BZ * SPLITS, TPB, smem>>>(feat, W, idx, pred, cla, seg, out);
}